// round 15
// baseline (speedup 1.0000x reference)
#include <cuda_runtime.h>
#include <cuda_fp16.h>
#include <cstdint>

#define N_NODES 50000
#define E_EDGES 500000
#define H_DIM   128
#define ROW_F   512          // 4 channels * 128 floats per node
#define MAXDEG  64

// ---------------------------------------------------------------------------
// Global scratch
// ---------------------------------------------------------------------------
__device__ __half g_xh[(size_t)N_NODES * ROW_F];   // fp16 x
__device__ __half g_Wh[4 * 128 * 256];             // [c][n][k] fp16 stacked W
__device__ int g_is64;
__device__ int g_cnt[N_NODES];                     // degree counters
__device__ int g_ecols[(size_t)N_NODES * MAXDEG];  // ELL neighbor lists

// ---------------------------------------------------------------------------
// helpers
// ---------------------------------------------------------------------------
__device__ __forceinline__ uint32_t smem_u32(const void* p) {
    uint32_t a;
    asm("{ .reg .u64 t; cvta.to.shared.u64 t, %1; cvt.u32.u64 %0, t; }"
        : "=r"(a) : "l"(p));
    return a;
}

#define SW128(o) ((o) ^ (((o) >> 3) & 0x70))

__device__ __forceinline__ void ldsm_x4(uint32_t addr, uint32_t& r0, uint32_t& r1,
                                        uint32_t& r2, uint32_t& r3) {
    asm volatile("ldmatrix.sync.aligned.m8n8.x4.shared.b16 {%0,%1,%2,%3}, [%4];"
                 : "=r"(r0), "=r"(r1), "=r"(r2), "=r"(r3) : "r"(addr));
}

__device__ __forceinline__ void mma16816h(float* c, const uint32_t* a,
                                          uint32_t b0, uint32_t b1) {
    asm volatile(
        "mma.sync.aligned.m16n8k16.row.col.f32.f16.f16.f32 "
        "{%0,%1,%2,%3}, {%4,%5,%6,%7}, {%8,%9}, {%0,%1,%2,%3};"
        : "+f"(c[0]), "+f"(c[1]), "+f"(c[2]), "+f"(c[3])
        : "r"(a[0]), "r"(a[1]), "r"(a[2]), "r"(a[3]), "r"(b0), "r"(b1));
}

__device__ __forceinline__ void cp_async16(uint32_t smem_addr, const void* gptr) {
    asm volatile("cp.async.cg.shared.global [%0], [%1], 16;"
                 :: "r"(smem_addr), "l"(gptr) : "memory");
}
__device__ __forceinline__ void cp_commit() {
    asm volatile("cp.async.commit_group;" ::: "memory");
}
template <int N>
__device__ __forceinline__ void cp_wait() {
    asm volatile("cp.async.wait_group %0;" :: "n"(N) : "memory");
}

// accumulate 8 fp16 values (packed in uint4) into float acc[8]
__device__ __forceinline__ void add8(float* a, uint4 v) {
    float2 f;
    f = __half22float2(*(__half2*)&v.x); a[0] += f.x; a[1] += f.y;
    f = __half22float2(*(__half2*)&v.y); a[2] += f.x; a[3] += f.y;
    f = __half22float2(*(__half2*)&v.z); a[4] += f.x; a[5] += f.y;
    f = __half22float2(*(__half2*)&v.w); a[6] += f.x; a[7] += f.y;
}

// ---------------------------------------------------------------------------
// edge index fetch with dtype branch
// ---------------------------------------------------------------------------
__device__ __forceinline__ int edge_idx(const void* ei_raw, size_t i) {
    if (g_is64) return (int)((const long long*)ei_raw)[i];
    return ((const int*)ei_raw)[i];
}

// ---------------------------------------------------------------------------
// Phase 0a: zero degree counters + detect edge dtype (one launch)
// ---------------------------------------------------------------------------
__global__ __launch_bounds__(256)
void detect_zero_kernel(const int* __restrict__ ei32) {
    int i = blockIdx.x * blockDim.x + threadIdx.x;
    if (i < N_NODES) g_cnt[i] = 0;
    if (i == 0) {
        int all_zero = 1;
        for (int k = 0; k < 128; k++) {
            if (ei32[2 * k + 1] != 0) { all_zero = 0; break; }
        }
        g_is64 = all_zero;
    }
}

// ---------------------------------------------------------------------------
// Phase 0b: fused prep — x->fp16 | weights->fp16 | ELL edge scatter
// ---------------------------------------------------------------------------
#define PXB 25000   // 6.4M float4 / 256
#define PWB 512     // 131072 weight elems / 256
#define EB  1954    // 500000 edges / 256 (ceil)

__global__ __launch_bounds__(256)
void fused_prep_kernel(const float* __restrict__ x,
                       const void* __restrict__ ei_raw,
                       const float* __restrict__ Wsrel,
                       const float* __restrict__ Wsroot,
                       const float* __restrict__ Wvrel,
                       const float* __restrict__ Wvroot) {
    int b = blockIdx.x;
    int tid = threadIdx.x;
    if (b < PXB) {
        // x fp32 -> fp16
        size_t i = (size_t)b * 256 + tid;
        float4 v = __ldg((const float4*)x + i);
        __half2 h0 = __floats2half2_rn(v.x, v.y);
        __half2 h1 = __floats2half2_rn(v.z, v.w);
        uint2 hp;
        hp.x = *(uint32_t*)&h0;
        hp.y = *(uint32_t*)&h1;
        ((uint2*)g_xh)[i] = hp;
    } else if (b < PXB + PWB) {
        // stacked fp16 weights, [c][n][k]
        int idx = (b - PXB) * 256 + tid;      // 0..131071
        int c = idx >> 15;
        int r = idx & 32767;
        int n = r >> 8;
        int k = r & 255;
        const float* root = (c == 0) ? Wsroot : Wvroot;
        const float* rel  = (c == 0) ? Wsrel  : Wvrel;
        float w = (k < 128) ? __ldg(root + n * 128 + k)
                            : __ldg(rel  + n * 128 + (k - 128));
        g_Wh[idx] = __float2half_rn(w);
    } else {
        // ELL edge scatter: position via atomic degree counter
        int e = (b - PXB - PWB) * 256 + tid;
        if (e < E_EDGES) {
            int row = edge_idx(ei_raw, e);
            int col = edge_idx(ei_raw, (size_t)E_EDGES + e);
            int pos = atomicAdd(&g_cnt[row], 1);
            if (pos < MAXDEG)
                g_ecols[(size_t)row * MAXDEG + pos] = col;
        }
    }
}

// ---------------------------------------------------------------------------
// Fused transform: in-kernel ELL aggregation (per block/channel slice)
//   + fp16 HMMA GEMM, 2-stage cp.async pipeline.
//   Block 256 nodes x 128 outs, 512 threads (16 warps, warp tile 64x32).
//   K chunks: kc 0,1 read x via cp.async; kc 2,3 read agg from smem buffer
//   filled by the in-kernel gather (overlapped with kc 0,1 loads/compute).
// ---------------------------------------------------------------------------
#define NSTAGE   2
#define STAGE_SZ 49152
#define OFF_A    0
#define OFF_W    32768
#define OFF_AGG  (NSTAGE * STAGE_SZ)          // 98304
#define AGG_SZ   32768                        // per-chunk agg buffer
#define SM_TOTAL (OFF_AGG + 2 * AGG_SZ)       // 163840
#define BM       256

__global__ __launch_bounds__(512, 1)
void transform_mma_kernel(const float* __restrict__ bsr,
                          float* __restrict__ out) {
    extern __shared__ char smem[];
    const uint32_t sb = smem_u32(smem);
    const int tid  = threadIdx.x;
    const int wid  = tid >> 5;
    const int lane = tid & 31;
    const int c      = blockIdx.y;
    const int node0  = blockIdx.x * BM;
    const int warp_m = (wid & 3) * 64;    // 4 warps along m, 64 rows each
    const int warp_n = (wid >> 2) * 32;   // 4 warps along n, 32 cols each

    // loader coords: 512 threads, 16B each -> 64 rows/iter
    const int lu = tid & 7;        // 16B unit within 128B row
    const int lr = tid >> 3;       // row 0..63

    const size_t wcbase = (size_t)c * 128 * 256;

    auto issue_chunk = [&](int kc, int st) {
        const uint32_t base = sb + st * STAGE_SZ;
        if (kc < 2) {
            // A: 256 rows x 64 halves of x
            const int koff = kc * 64 + c * H_DIM;
            #pragma unroll
            for (int it = 0; it < 4; it++) {
                int row = lr + it * 64;
                uint32_t sw = SW128((uint32_t)(row * 128 + lu * 16));
                int node = node0 + row;
                if (node < N_NODES) {
                    cp_async16(base + OFF_A + sw,
                               g_xh + (size_t)node * ROW_F + koff + lu * 8);
                } else {
                    uint4 z = make_uint4(0, 0, 0, 0);
                    *(uint4*)(smem + st * STAGE_SZ + OFF_A + sw) = z;
                }
            }
        }
        // W: 128 rows x 64 halves
        #pragma unroll
        for (int it = 0; it < 2; it++) {
            int row = lr + it * 64;
            uint32_t sw = SW128((uint32_t)(row * 128 + lu * 16));
            cp_async16(base + OFF_W + sw,
                       g_Wh + wcbase + (size_t)row * 256 + kc * 64 + lu * 8);
        }
        cp_commit();
    };

    issue_chunk(0, 0);
    issue_chunk(1, 1);

    // ---- in-kernel aggregation: 256 nodes x 128-half channel slice ----
    // 16 lanes per node (one uint4 = 8 halves each), 32 nodes per pass.
    {
        const int u  = tid & 15;       // uint4 index within slice (0..15)
        const int nl = tid >> 4;       // node sub-index (0..31)
        const int buf = u >> 3;        // 0 -> kc=2 buffer, 1 -> kc=3 buffer
        const int up  = u & 7;         // 16B unit within chunk row
        #pragma unroll 1
        for (int pass = 0; pass < 8; pass++) {
            int nloc = pass * 32 + nl;             // 0..255
            int node = node0 + nloc;
            float acc[8];
            #pragma unroll
            for (int q = 0; q < 8; q++) acc[q] = 0.f;
            if (node < N_NODES) {
                int cnt = __ldg(&g_cnt[node]);
                if (cnt > MAXDEG) cnt = MAXDEG;
                const int* cols = g_ecols + (size_t)node * MAXDEG;
                int j = 0;
                for (; j + 1 < cnt; j += 2) {
                    int c0 = __ldg(cols + j);
                    int c1 = __ldg(cols + j + 1);
                    uint4 v0 = __ldg((const uint4*)(g_xh + (size_t)c0 * ROW_F + c * H_DIM) + u);
                    uint4 v1 = __ldg((const uint4*)(g_xh + (size_t)c1 * ROW_F + c * H_DIM) + u);
                    add8(acc, v0);
                    add8(acc, v1);
                }
                if (j < cnt) {
                    int c0 = __ldg(cols + j);
                    uint4 v0 = __ldg((const uint4*)(g_xh + (size_t)c0 * ROW_F + c * H_DIM) + u);
                    add8(acc, v0);
                }
            }
            __half2 h0 = __floats2half2_rn(acc[0], acc[1]);
            __half2 h1 = __floats2half2_rn(acc[2], acc[3]);
            __half2 h2 = __floats2half2_rn(acc[4], acc[5]);
            __half2 h3 = __floats2half2_rn(acc[6], acc[7]);
            uint4 o;
            o.x = *(uint32_t*)&h0; o.y = *(uint32_t*)&h1;
            o.z = *(uint32_t*)&h2; o.w = *(uint32_t*)&h3;
            uint32_t sw = SW128((uint32_t)(nloc * 128 + up * 16));
            *(uint4*)(smem + OFF_AGG + buf * AGG_SZ + sw) = o;
        }
    }

    // ---- MMA accumulators (init after gather to keep liveness disjoint) ----
    float acc[4][4][4];     // [mt][n8-tile][frag]
    #pragma unroll
    for (int mt = 0; mt < 4; mt++)
        #pragma unroll
        for (int j = 0; j < 4; j++)
            #pragma unroll
            for (int q = 0; q < 4; q++) acc[mt][j][q] = 0.f;

    // ldmatrix lane-address components
    const int a_row_l = lane & 15;
    const int a_koff  = (lane >> 4) << 4;
    const int b_row_l = ((lane >> 4) << 3) + (lane & 7);
    const int b_koff  = ((lane >> 3) & 1) << 4;

    for (int kc = 0; kc < 4; kc++) {
        const int st = kc & 1;
        if (kc < 3) cp_wait<1>(); else cp_wait<0>();
        __syncthreads();   // also orders the gather smem stores before kc>=2

        const uint32_t base  = sb + st * STAGE_SZ;
        const uint32_t abase = (kc < 2) ? (base + OFF_A)
                                        : (sb + OFF_AGG + (kc - 2) * AGG_SZ);
        #pragma unroll
        for (int ks = 0; ks < 4; ks++) {
            uint32_t ah[4][4];
            #pragma unroll
            for (int mt = 0; mt < 4; mt++) {
                uint32_t sw = SW128((uint32_t)((warp_m + mt * 16 + a_row_l) * 128
                                               + ks * 32 + a_koff));
                ldsm_x4(abase + sw, ah[mt][0], ah[mt][1], ah[mt][2], ah[mt][3]);
            }
            #pragma unroll
            for (int np = 0; np < 2; np++) {
                uint32_t sw = SW128((uint32_t)((warp_n + np * 16 + b_row_l) * 128
                                               + ks * 32 + b_koff));
                uint32_t bh0, bh1, bh2, bh3;
                ldsm_x4(base + OFF_W + sw, bh0, bh1, bh2, bh3);
                #pragma unroll
                for (int mt = 0; mt < 4; mt++) {
                    mma16816h(acc[mt][np * 2 + 0], ah[mt], bh0, bh1);
                    mma16816h(acc[mt][np * 2 + 1], ah[mt], bh2, bh3);
                }
            }
        }
        __syncthreads();
        if (kc + NSTAGE < 4) issue_chunk(kc + NSTAGE, st);
    }

    // ---- epilogue ----
    const int erow = lane >> 2;
    const int ecol = (lane & 3) * 2;
    #pragma unroll
    for (int mt = 0; mt < 4; mt++) {
        #pragma unroll
        for (int j = 0; j < 4; j++) {
            int col = warp_n + j * 8 + ecol;
            float b0 = 0.f, b1 = 0.f;
            if (c == 0) { b0 = __ldg(bsr + col); b1 = __ldg(bsr + col + 1); }
            int r0 = node0 + warp_m + mt * 16 + erow;
            int r1 = r0 + 8;
            if (r0 < N_NODES) {
                float2 v = make_float2(acc[mt][j][0] + b0, acc[mt][j][1] + b1);
                *(float2*)(out + (size_t)r0 * ROW_F + (size_t)c * H_DIM + col) = v;
            }
            if (r1 < N_NODES) {
                float2 v = make_float2(acc[mt][j][2] + b0, acc[mt][j][3] + b1);
                *(float2*)(out + (size_t)r1 * ROW_F + (size_t)c * H_DIM + col) = v;
            }
        }
    }
}

// ---------------------------------------------------------------------------
// Launch
// ---------------------------------------------------------------------------
extern "C" void kernel_launch(void* const* d_in, const int* in_sizes, int n_in,
                              void* d_out, int out_size) {
    const float* x      = (const float*)d_in[0];
    const void*  ei     = d_in[1];
    const float* Wsrel  = (const float*)d_in[2];
    const float* Wsroot = (const float*)d_in[3];
    const float* bsr    = (const float*)d_in[4];
    const float* Wvrel  = (const float*)d_in[5];
    const float* Wvroot = (const float*)d_in[6];
    float*       out    = (float*)d_out;

    cudaFuncSetAttribute(transform_mma_kernel,
                         cudaFuncAttributeMaxDynamicSharedMemorySize, SM_TOTAL);

    // Phase 0: zero degree counters + dtype detect
    detect_zero_kernel<<<(N_NODES + 255) / 256, 256>>>((const int*)ei);

    // Phase 1: fused prep (x fp16 | W fp16 | ELL scatter)
    fused_prep_kernel<<<PXB + PWB + EB, 256>>>(x, ei, Wsrel, Wsroot, Wvrel, Wvroot);

    // Phase 2: fused aggregation + transform
    {
        dim3 grid((N_NODES + BM - 1) / BM, 4);
        transform_mma_kernel<<<grid, 512, SM_TOTAL>>>(bsr, out);
    }
}

// round 16
// speedup vs baseline: 1.5425x; 1.5425x over previous
#include <cuda_runtime.h>
#include <cuda_fp16.h>
#include <cstdint>

#define N_NODES 50000
#define E_EDGES 500000
#define H_DIM   128
#define ROW_F   512          // 4 channels * 128 floats per node
#define MAXDEG  64

// ---------------------------------------------------------------------------
// Global scratch
// ---------------------------------------------------------------------------
__device__ __half g_xh[(size_t)N_NODES * ROW_F];   // fp16 x
__device__ __half g_ah[(size_t)N_NODES * ROW_F];   // fp16 agg
__device__ __half g_Wh[4 * 128 * 256];             // [c][n][k] fp16 stacked W
__device__ int g_is64;
__device__ int g_cnt[N_NODES];                     // degree counters
__device__ int g_ecols[(size_t)N_NODES * MAXDEG];  // ELL neighbor lists

// ---------------------------------------------------------------------------
// helpers
// ---------------------------------------------------------------------------
__device__ __forceinline__ uint32_t smem_u32(const void* p) {
    uint32_t a;
    asm("{ .reg .u64 t; cvta.to.shared.u64 t, %1; cvt.u32.u64 %0, t; }"
        : "=r"(a) : "l"(p));
    return a;
}

#define SW128(o) ((o) ^ (((o) >> 3) & 0x70))

__device__ __forceinline__ void ldsm_x4(uint32_t addr, uint32_t& r0, uint32_t& r1,
                                        uint32_t& r2, uint32_t& r3) {
    asm volatile("ldmatrix.sync.aligned.m8n8.x4.shared.b16 {%0,%1,%2,%3}, [%4];"
                 : "=r"(r0), "=r"(r1), "=r"(r2), "=r"(r3) : "r"(addr));
}

__device__ __forceinline__ void mma16816h(float* c, const uint32_t* a,
                                          uint32_t b0, uint32_t b1) {
    asm volatile(
        "mma.sync.aligned.m16n8k16.row.col.f32.f16.f16.f32 "
        "{%0,%1,%2,%3}, {%4,%5,%6,%7}, {%8,%9}, {%0,%1,%2,%3};"
        : "+f"(c[0]), "+f"(c[1]), "+f"(c[2]), "+f"(c[3])
        : "r"(a[0]), "r"(a[1]), "r"(a[2]), "r"(a[3]), "r"(b0), "r"(b1));
}

__device__ __forceinline__ void cp_async16(uint32_t smem_addr, const void* gptr) {
    asm volatile("cp.async.cg.shared.global [%0], [%1], 16;"
                 :: "r"(smem_addr), "l"(gptr) : "memory");
}
__device__ __forceinline__ void cp_commit() {
    asm volatile("cp.async.commit_group;" ::: "memory");
}
template <int N>
__device__ __forceinline__ void cp_wait() {
    asm volatile("cp.async.wait_group %0;" :: "n"(N) : "memory");
}

// accumulate 8 fp16 values (packed in uint4) into float acc[8]
__device__ __forceinline__ void add8(float* a, uint4 v) {
    float2 f;
    f = __half22float2(*(__half2*)&v.x); a[0] += f.x; a[1] += f.y;
    f = __half22float2(*(__half2*)&v.y); a[2] += f.x; a[3] += f.y;
    f = __half22float2(*(__half2*)&v.z); a[4] += f.x; a[5] += f.y;
    f = __half22float2(*(__half2*)&v.w); a[6] += f.x; a[7] += f.y;
}

// ---------------------------------------------------------------------------
// edge index fetch with dtype branch
// ---------------------------------------------------------------------------
__device__ __forceinline__ int edge_idx(const void* ei_raw, size_t i) {
    if (g_is64) return (int)((const long long*)ei_raw)[i];
    return ((const int*)ei_raw)[i];
}

// ---------------------------------------------------------------------------
// Phase 0a: zero degree counters + detect edge dtype (one launch)
// ---------------------------------------------------------------------------
__global__ __launch_bounds__(256)
void detect_zero_kernel(const int* __restrict__ ei32) {
    int i = blockIdx.x * blockDim.x + threadIdx.x;
    if (i < N_NODES) g_cnt[i] = 0;
    if (i == 0) {
        int all_zero = 1;
        for (int k = 0; k < 128; k++) {
            if (ei32[2 * k + 1] != 0) { all_zero = 0; break; }
        }
        g_is64 = all_zero;
    }
}

// ---------------------------------------------------------------------------
// Phase 0b: fused prep — x->fp16 | weights->fp16 | ELL edge scatter
// ---------------------------------------------------------------------------
#define PXB 25000   // 6.4M float4 / 256
#define PWB 512     // 131072 weight elems / 256
#define EB  1954    // 500000 edges / 256 (ceil)

__global__ __launch_bounds__(256)
void fused_prep_kernel(const float* __restrict__ x,
                       const void* __restrict__ ei_raw,
                       const float* __restrict__ Wsrel,
                       const float* __restrict__ Wsroot,
                       const float* __restrict__ Wvrel,
                       const float* __restrict__ Wvroot) {
    int b = blockIdx.x;
    int tid = threadIdx.x;
    if (b < PXB) {
        // x fp32 -> fp16
        size_t i = (size_t)b * 256 + tid;
        float4 v = __ldg((const float4*)x + i);
        __half2 h0 = __floats2half2_rn(v.x, v.y);
        __half2 h1 = __floats2half2_rn(v.z, v.w);
        uint2 hp;
        hp.x = *(uint32_t*)&h0;
        hp.y = *(uint32_t*)&h1;
        ((uint2*)g_xh)[i] = hp;
    } else if (b < PXB + PWB) {
        // stacked fp16 weights, [c][n][k]
        int idx = (b - PXB) * 256 + tid;      // 0..131071
        int c = idx >> 15;
        int r = idx & 32767;
        int n = r >> 8;
        int k = r & 255;
        const float* root = (c == 0) ? Wsroot : Wvroot;
        const float* rel  = (c == 0) ? Wsrel  : Wvrel;
        float w = (k < 128) ? __ldg(root + n * 128 + k)
                            : __ldg(rel  + n * 128 + (k - 128));
        g_Wh[idx] = __float2half_rn(w);
    } else {
        // ELL edge scatter: position via atomic degree counter
        int e = (b - PXB - PWB) * 256 + tid;
        if (e < E_EDGES) {
            int row = edge_idx(ei_raw, e);
            int col = edge_idx(ei_raw, (size_t)E_EDGES + e);
            int pos = atomicAdd(&g_cnt[row], 1);
            if (pos < MAXDEG)
                g_ecols[(size_t)row * MAXDEG + pos] = col;
        }
    }
}

// ---------------------------------------------------------------------------
// ELL aggregation: gather fp16 rows (1KB/edge via L2), fp32 accumulate,
// fp16 out. 64 lanes per node, 4 nodes per 256-thread block.
// ---------------------------------------------------------------------------
__global__ __launch_bounds__(256)
void csr_agg_kernel() {
    int node = blockIdx.x * 4 + (threadIdx.x >> 6);
    int lane = threadIdx.x & 63;
    if (node >= N_NODES) return;

    int cnt = __ldg(&g_cnt[node]);
    if (cnt > MAXDEG) cnt = MAXDEG;
    const int* cols = g_ecols + (size_t)node * MAXDEG;

    float acc[8];
    #pragma unroll
    for (int q = 0; q < 8; q++) acc[q] = 0.f;

    int j = 0;
    for (; j + 1 < cnt; j += 2) {
        int c0 = __ldg(cols + j);
        int c1 = __ldg(cols + j + 1);
        uint4 v0 = __ldg((const uint4*)(g_xh + (size_t)c0 * ROW_F) + lane);
        uint4 v1 = __ldg((const uint4*)(g_xh + (size_t)c1 * ROW_F) + lane);
        add8(acc, v0);
        add8(acc, v1);
    }
    if (j < cnt) {
        int c0 = __ldg(cols + j);
        uint4 v0 = __ldg((const uint4*)(g_xh + (size_t)c0 * ROW_F) + lane);
        add8(acc, v0);
    }

    __half2 h0 = __floats2half2_rn(acc[0], acc[1]);
    __half2 h1 = __floats2half2_rn(acc[2], acc[3]);
    __half2 h2 = __floats2half2_rn(acc[4], acc[5]);
    __half2 h3 = __floats2half2_rn(acc[6], acc[7]);
    uint4 o;
    o.x = *(uint32_t*)&h0; o.y = *(uint32_t*)&h1;
    o.z = *(uint32_t*)&h2; o.w = *(uint32_t*)&h3;
    ((uint4*)(g_ah + (size_t)node * ROW_F))[lane] = o;
}

// ---------------------------------------------------------------------------
// Transform: fp16 HMMA GEMM, 2-stage cp.async pipeline, 2 CTAs/SM.
//   Block 128 nodes x 128 outs, 256 threads (8 warps, warp tile 64x32).
//   K=256 stacked [x | agg], chunked 4 x 64. Stage = A(16KB) + W(16KB).
// ---------------------------------------------------------------------------
#define NSTAGE   2
#define STAGE_SZ 32768
#define OFF_A    0
#define OFF_W    16384
#define SM_TOTAL (NSTAGE * STAGE_SZ)   // 65536
#define BM       128

__global__ __launch_bounds__(256, 2)
void transform_mma_kernel(const float* __restrict__ bsr,
                          float* __restrict__ out) {
    extern __shared__ char smem[];
    const uint32_t sb = smem_u32(smem);
    const int tid  = threadIdx.x;
    const int wid  = tid >> 5;
    const int lane = tid & 31;
    const int c      = blockIdx.y;
    const int node0  = blockIdx.x * BM;
    const int warp_m = (wid & 1) * 64;    // 2 warps along m, 64 rows each
    const int warp_n = (wid >> 1) * 32;   // 4 warps along n, 32 cols each

    float acc[4][4][4];     // [mt][n8-tile][frag]
    #pragma unroll
    for (int mt = 0; mt < 4; mt++)
        #pragma unroll
        for (int j = 0; j < 4; j++)
            #pragma unroll
            for (int q = 0; q < 4; q++) acc[mt][j][q] = 0.f;

    // loader coords: 256 threads, 16B each -> 32 rows per pass
    const int lu = tid & 7;        // 16B unit within 128B row
    const int lr = tid >> 3;       // row 0..31

    // ldmatrix lane-address components
    const int a_row_l = lane & 15;
    const int a_koff  = (lane >> 4) << 4;
    const int b_row_l = ((lane >> 4) << 3) + (lane & 7);
    const int b_koff  = ((lane >> 3) & 1) << 4;

    const size_t wcbase = (size_t)c * 128 * 256;

    auto issue_chunk = [&](int kc, int st) {
        const uint32_t base = sb + st * STAGE_SZ;
        const __half* src = (kc < 2) ? g_xh : g_ah;
        const int koff = (kc & 1) * 64 + c * H_DIM;
        // A: 128 rows x 64 halves (4 passes)
        #pragma unroll
        for (int it = 0; it < 4; it++) {
            int row = lr + it * 32;
            uint32_t sw = SW128((uint32_t)(row * 128 + lu * 16));
            int node = node0 + row;
            if (node < N_NODES) {
                cp_async16(base + OFF_A + sw,
                           src + (size_t)node * ROW_F + koff + lu * 8);
            } else {
                uint4 z = make_uint4(0, 0, 0, 0);
                *(uint4*)(smem + st * STAGE_SZ + OFF_A + sw) = z;
            }
        }
        // W: 128 rows x 64 halves (4 passes)
        #pragma unroll
        for (int it = 0; it < 4; it++) {
            int row = lr + it * 32;
            uint32_t sw = SW128((uint32_t)(row * 128 + lu * 16));
            cp_async16(base + OFF_W + sw,
                       g_Wh + wcbase + (size_t)row * 256 + kc * 64 + lu * 8);
        }
        cp_commit();
    };

    issue_chunk(0, 0);
    issue_chunk(1, 1);

    for (int kc = 0; kc < 4; kc++) {
        const int st = kc & 1;
        if (kc < 3) cp_wait<1>(); else cp_wait<0>();
        __syncthreads();

        const uint32_t base = sb + st * STAGE_SZ;
        #pragma unroll
        for (int ks = 0; ks < 4; ks++) {
            uint32_t ah[4][4];
            #pragma unroll
            for (int mt = 0; mt < 4; mt++) {
                uint32_t sw = SW128((uint32_t)((warp_m + mt * 16 + a_row_l) * 128
                                               + ks * 32 + a_koff));
                ldsm_x4(base + OFF_A + sw, ah[mt][0], ah[mt][1], ah[mt][2], ah[mt][3]);
            }
            #pragma unroll
            for (int np = 0; np < 2; np++) {
                uint32_t sw = SW128((uint32_t)((warp_n + np * 16 + b_row_l) * 128
                                               + ks * 32 + b_koff));
                uint32_t bh0, bh1, bh2, bh3;
                ldsm_x4(base + OFF_W + sw, bh0, bh1, bh2, bh3);
                #pragma unroll
                for (int mt = 0; mt < 4; mt++) {
                    mma16816h(acc[mt][np * 2 + 0], ah[mt], bh0, bh1);
                    mma16816h(acc[mt][np * 2 + 1], ah[mt], bh2, bh3);
                }
            }
        }
        __syncthreads();
        if (kc + NSTAGE < 4) issue_chunk(kc + NSTAGE, st);
    }

    // ---- epilogue ----
    const int erow = lane >> 2;
    const int ecol = (lane & 3) * 2;
    #pragma unroll
    for (int mt = 0; mt < 4; mt++) {
        #pragma unroll
        for (int j = 0; j < 4; j++) {
            int col = warp_n + j * 8 + ecol;
            float b0 = 0.f, b1 = 0.f;
            if (c == 0) { b0 = __ldg(bsr + col); b1 = __ldg(bsr + col + 1); }
            int r0 = node0 + warp_m + mt * 16 + erow;
            int r1 = r0 + 8;
            if (r0 < N_NODES) {
                float2 v = make_float2(acc[mt][j][0] + b0, acc[mt][j][1] + b1);
                *(float2*)(out + (size_t)r0 * ROW_F + (size_t)c * H_DIM + col) = v;
            }
            if (r1 < N_NODES) {
                float2 v = make_float2(acc[mt][j][2] + b0, acc[mt][j][3] + b1);
                *(float2*)(out + (size_t)r1 * ROW_F + (size_t)c * H_DIM + col) = v;
            }
        }
    }
}

// ---------------------------------------------------------------------------
// Launch
// ---------------------------------------------------------------------------
extern "C" void kernel_launch(void* const* d_in, const int* in_sizes, int n_in,
                              void* d_out, int out_size) {
    const float* x      = (const float*)d_in[0];
    const void*  ei     = d_in[1];
    const float* Wsrel  = (const float*)d_in[2];
    const float* Wsroot = (const float*)d_in[3];
    const float* bsr    = (const float*)d_in[4];
    const float* Wvrel  = (const float*)d_in[5];
    const float* Wvroot = (const float*)d_in[6];
    float*       out    = (float*)d_out;

    cudaFuncSetAttribute(transform_mma_kernel,
                         cudaFuncAttributeMaxDynamicSharedMemorySize, SM_TOTAL);

    // Phase 0: zero degree counters + dtype detect
    detect_zero_kernel<<<(N_NODES + 255) / 256, 256>>>((const int*)ei);

    // Phase 1: fused prep (x fp16 | W fp16 | ELL scatter)
    fused_prep_kernel<<<PXB + PWB + EB, 256>>>(x, ei, Wsrel, Wsroot, Wvrel, Wvroot);

    // Phase 2: ELL aggregation
    csr_agg_kernel<<<(N_NODES + 3) / 4, 256>>>();

    // Phase 3: transform (fp16 HMMA, 128x128 tile, 8 warps, 2 CTAs/SM)
    {
        dim3 grid((N_NODES + BM - 1) / BM, 4);
        transform_mma_kernel<<<grid, 256, SM_TOTAL>>>(bsr, out);
    }
}

// round 17
// speedup vs baseline: 1.5602x; 1.0115x over previous
#include <cuda_runtime.h>
#include <cuda_fp16.h>
#include <cstdint>

#define N_NODES 50000
#define E_EDGES 500000
#define H_DIM   128
#define ROW_F   512          // 4 channels * 128 floats per node
#define MAXDEG  64

// ---------------------------------------------------------------------------
// Global scratch
// ---------------------------------------------------------------------------
__device__ __half g_xh[(size_t)N_NODES * ROW_F];   // fp16 x
__device__ __half g_ah[(size_t)N_NODES * ROW_F];   // fp16 agg
__device__ __half g_Wh[4 * 128 * 256];             // [c][n][k] fp16 stacked W
__device__ int g_is64;
__device__ int g_cnt[N_NODES];                     // degree counters
__device__ int g_ecols[(size_t)N_NODES * MAXDEG];  // ELL neighbor lists

// ---------------------------------------------------------------------------
// helpers
// ---------------------------------------------------------------------------
__device__ __forceinline__ uint32_t smem_u32(const void* p) {
    uint32_t a;
    asm("{ .reg .u64 t; cvta.to.shared.u64 t, %1; cvt.u32.u64 %0, t; }"
        : "=r"(a) : "l"(p));
    return a;
}

#define SW128(o) ((o) ^ (((o) >> 3) & 0x70))

__device__ __forceinline__ void ldsm_x4(uint32_t addr, uint32_t& r0, uint32_t& r1,
                                        uint32_t& r2, uint32_t& r3) {
    asm volatile("ldmatrix.sync.aligned.m8n8.x4.shared.b16 {%0,%1,%2,%3}, [%4];"
                 : "=r"(r0), "=r"(r1), "=r"(r2), "=r"(r3) : "r"(addr));
}

__device__ __forceinline__ void mma16816h(float* c, const uint32_t* a,
                                          uint32_t b0, uint32_t b1) {
    asm volatile(
        "mma.sync.aligned.m16n8k16.row.col.f32.f16.f16.f32 "
        "{%0,%1,%2,%3}, {%4,%5,%6,%7}, {%8,%9}, {%0,%1,%2,%3};"
        : "+f"(c[0]), "+f"(c[1]), "+f"(c[2]), "+f"(c[3])
        : "r"(a[0]), "r"(a[1]), "r"(a[2]), "r"(a[3]), "r"(b0), "r"(b1));
}

__device__ __forceinline__ void cp_async16(uint32_t smem_addr, const void* gptr) {
    asm volatile("cp.async.cg.shared.global [%0], [%1], 16;"
                 :: "r"(smem_addr), "l"(gptr) : "memory");
}
__device__ __forceinline__ void cp_commit() {
    asm volatile("cp.async.commit_group;" ::: "memory");
}
template <int N>
__device__ __forceinline__ void cp_wait() {
    asm volatile("cp.async.wait_group %0;" :: "n"(N) : "memory");
}

// accumulate 8 fp16 values (packed in uint4) into float acc[8]
__device__ __forceinline__ void add8(float* a, uint4 v) {
    float2 f;
    f = __half22float2(*(__half2*)&v.x); a[0] += f.x; a[1] += f.y;
    f = __half22float2(*(__half2*)&v.y); a[2] += f.x; a[3] += f.y;
    f = __half22float2(*(__half2*)&v.z); a[4] += f.x; a[5] += f.y;
    f = __half22float2(*(__half2*)&v.w); a[6] += f.x; a[7] += f.y;
}

// ---------------------------------------------------------------------------
// edge index fetch with dtype branch
// ---------------------------------------------------------------------------
__device__ __forceinline__ int edge_idx(const void* ei_raw, size_t i) {
    if (g_is64) return (int)((const long long*)ei_raw)[i];
    return ((const int*)ei_raw)[i];
}

// ---------------------------------------------------------------------------
// Phase 0a: zero degree counters + detect edge dtype (one launch)
// ---------------------------------------------------------------------------
__global__ __launch_bounds__(256)
void detect_zero_kernel(const int* __restrict__ ei32) {
    int i = blockIdx.x * blockDim.x + threadIdx.x;
    if (i < N_NODES) g_cnt[i] = 0;
    if (i == 0) {
        int all_zero = 1;
        for (int k = 0; k < 128; k++) {
            if (ei32[2 * k + 1] != 0) { all_zero = 0; break; }
        }
        g_is64 = all_zero;
    }
}

// ---------------------------------------------------------------------------
// Phase 0b: fused prep — x->fp16 | weights->fp16 | ELL edge scatter
// ---------------------------------------------------------------------------
#define PXB 25000   // 6.4M float4 / 256
#define PWB 512     // 131072 weight elems / 256
#define EB  1954    // 500000 edges / 256 (ceil)

__global__ __launch_bounds__(256)
void fused_prep_kernel(const float* __restrict__ x,
                       const void* __restrict__ ei_raw,
                       const float* __restrict__ Wsrel,
                       const float* __restrict__ Wsroot,
                       const float* __restrict__ Wvrel,
                       const float* __restrict__ Wvroot) {
    int b = blockIdx.x;
    int tid = threadIdx.x;
    if (b < PXB) {
        // x fp32 -> fp16
        size_t i = (size_t)b * 256 + tid;
        float4 v = __ldg((const float4*)x + i);
        __half2 h0 = __floats2half2_rn(v.x, v.y);
        __half2 h1 = __floats2half2_rn(v.z, v.w);
        uint2 hp;
        hp.x = *(uint32_t*)&h0;
        hp.y = *(uint32_t*)&h1;
        ((uint2*)g_xh)[i] = hp;
    } else if (b < PXB + PWB) {
        // stacked fp16 weights, [c][n][k]
        int idx = (b - PXB) * 256 + tid;      // 0..131071
        int c = idx >> 15;
        int r = idx & 32767;
        int n = r >> 8;
        int k = r & 255;
        const float* root = (c == 0) ? Wsroot : Wvroot;
        const float* rel  = (c == 0) ? Wsrel  : Wvrel;
        float w = (k < 128) ? __ldg(root + n * 128 + k)
                            : __ldg(rel  + n * 128 + (k - 128));
        g_Wh[idx] = __float2half_rn(w);
    } else {
        // ELL edge scatter: position via atomic degree counter
        int e = (b - PXB - PWB) * 256 + tid;
        if (e < E_EDGES) {
            int row = edge_idx(ei_raw, e);
            int col = edge_idx(ei_raw, (size_t)E_EDGES + e);
            int pos = atomicAdd(&g_cnt[row], 1);
            if (pos < MAXDEG)
                g_ecols[(size_t)row * MAXDEG + pos] = col;
        }
    }
}

// ---------------------------------------------------------------------------
// ELL aggregation: gather fp16 rows (1KB/edge via L2), fp32 accumulate,
// fp16 out. 64 lanes per node, 4 nodes per 256-thread block.
// ---------------------------------------------------------------------------
__global__ __launch_bounds__(256)
void csr_agg_kernel() {
    int node = blockIdx.x * 4 + (threadIdx.x >> 6);
    int lane = threadIdx.x & 63;
    if (node >= N_NODES) return;

    int cnt = __ldg(&g_cnt[node]);
    if (cnt > MAXDEG) cnt = MAXDEG;
    const int* cols = g_ecols + (size_t)node * MAXDEG;

    float acc[8];
    #pragma unroll
    for (int q = 0; q < 8; q++) acc[q] = 0.f;

    int j = 0;
    for (; j + 1 < cnt; j += 2) {
        int c0 = __ldg(cols + j);
        int c1 = __ldg(cols + j + 1);
        uint4 v0 = __ldg((const uint4*)(g_xh + (size_t)c0 * ROW_F) + lane);
        uint4 v1 = __ldg((const uint4*)(g_xh + (size_t)c1 * ROW_F) + lane);
        add8(acc, v0);
        add8(acc, v1);
    }
    if (j < cnt) {
        int c0 = __ldg(cols + j);
        uint4 v0 = __ldg((const uint4*)(g_xh + (size_t)c0 * ROW_F) + lane);
        add8(acc, v0);
    }

    __half2 h0 = __floats2half2_rn(acc[0], acc[1]);
    __half2 h1 = __floats2half2_rn(acc[2], acc[3]);
    __half2 h2 = __floats2half2_rn(acc[4], acc[5]);
    __half2 h3 = __floats2half2_rn(acc[6], acc[7]);
    uint4 o;
    o.x = *(uint32_t*)&h0; o.y = *(uint32_t*)&h1;
    o.z = *(uint32_t*)&h2; o.w = *(uint32_t*)&h3;
    ((uint4*)(g_ah + (size_t)node * ROW_F))[lane] = o;
}

// ---------------------------------------------------------------------------
// Transform: fp16 HMMA GEMM, 3-stage cp.async pipeline, 2 CTAs/SM.
//   Block 128 nodes x 128 outs, 256 threads (8 warps, warp tile 64x32).
//   K=256 stacked [x | agg], chunked 4 x 64. Stage = A(16KB) + W(16KB).
// ---------------------------------------------------------------------------
#define NSTAGE   3
#define STAGE_SZ 32768
#define OFF_A    0
#define OFF_W    16384
#define SM_TOTAL (NSTAGE * STAGE_SZ)   // 98304
#define BM       128

__global__ __launch_bounds__(256, 2)
void transform_mma_kernel(const float* __restrict__ bsr,
                          float* __restrict__ out) {
    extern __shared__ char smem[];
    const uint32_t sb = smem_u32(smem);
    const int tid  = threadIdx.x;
    const int wid  = tid >> 5;
    const int lane = tid & 31;
    const int c      = blockIdx.y;
    const int node0  = blockIdx.x * BM;
    const int warp_m = (wid & 1) * 64;    // 2 warps along m, 64 rows each
    const int warp_n = (wid >> 1) * 32;   // 4 warps along n, 32 cols each

    float acc[4][4][4];     // [mt][n8-tile][frag]
    #pragma unroll
    for (int mt = 0; mt < 4; mt++)
        #pragma unroll
        for (int j = 0; j < 4; j++)
            #pragma unroll
            for (int q = 0; q < 4; q++) acc[mt][j][q] = 0.f;

    // loader coords: 256 threads, 16B each -> 32 rows per pass
    const int lu = tid & 7;        // 16B unit within 128B row
    const int lr = tid >> 3;       // row 0..31

    // ldmatrix lane-address components
    const int a_row_l = lane & 15;
    const int a_koff  = (lane >> 4) << 4;
    const int b_row_l = ((lane >> 4) << 3) + (lane & 7);
    const int b_koff  = ((lane >> 3) & 1) << 4;

    const size_t wcbase = (size_t)c * 128 * 256;

    auto issue_chunk = [&](int kc, int st) {
        const uint32_t base = sb + st * STAGE_SZ;
        const __half* src = (kc < 2) ? g_xh : g_ah;
        const int koff = (kc & 1) * 64 + c * H_DIM;
        // A: 128 rows x 64 halves (4 passes)
        #pragma unroll
        for (int it = 0; it < 4; it++) {
            int row = lr + it * 32;
            uint32_t sw = SW128((uint32_t)(row * 128 + lu * 16));
            int node = node0 + row;
            if (node < N_NODES) {
                cp_async16(base + OFF_A + sw,
                           src + (size_t)node * ROW_F + koff + lu * 8);
            } else {
                uint4 z = make_uint4(0, 0, 0, 0);
                *(uint4*)(smem + st * STAGE_SZ + OFF_A + sw) = z;
            }
        }
        // W: 128 rows x 64 halves (4 passes)
        #pragma unroll
        for (int it = 0; it < 4; it++) {
            int row = lr + it * 32;
            uint32_t sw = SW128((uint32_t)(row * 128 + lu * 16));
            cp_async16(base + OFF_W + sw,
                       g_Wh + wcbase + (size_t)row * 256 + kc * 64 + lu * 8);
        }
        cp_commit();
    };

    issue_chunk(0, 0);
    issue_chunk(1, 1);
    issue_chunk(2, 2);

    for (int kc = 0; kc < 4; kc++) {
        const int st = kc % NSTAGE;
        if (kc <= 1)      cp_wait<2>();
        else if (kc == 2) cp_wait<1>();
        else              cp_wait<0>();
        __syncthreads();

        const uint32_t base = sb + st * STAGE_SZ;
        #pragma unroll
        for (int ks = 0; ks < 4; ks++) {
            uint32_t ah[4][4];
            #pragma unroll
            for (int mt = 0; mt < 4; mt++) {
                uint32_t sw = SW128((uint32_t)((warp_m + mt * 16 + a_row_l) * 128
                                               + ks * 32 + a_koff));
                ldsm_x4(base + OFF_A + sw, ah[mt][0], ah[mt][1], ah[mt][2], ah[mt][3]);
            }
            #pragma unroll
            for (int np = 0; np < 2; np++) {
                uint32_t sw = SW128((uint32_t)((warp_n + np * 16 + b_row_l) * 128
                                               + ks * 32 + b_koff));
                uint32_t bh0, bh1, bh2, bh3;
                ldsm_x4(base + OFF_W + sw, bh0, bh1, bh2, bh3);
                #pragma unroll
                for (int mt = 0; mt < 4; mt++) {
                    mma16816h(acc[mt][np * 2 + 0], ah[mt], bh0, bh1);
                    mma16816h(acc[mt][np * 2 + 1], ah[mt], bh2, bh3);
                }
            }
        }
        __syncthreads();
        if (kc + NSTAGE < 4) issue_chunk(kc + NSTAGE, st);
    }

    // ---- epilogue ----
    const int erow = lane >> 2;
    const int ecol = (lane & 3) * 2;
    #pragma unroll
    for (int mt = 0; mt < 4; mt++) {
        #pragma unroll
        for (int j = 0; j < 4; j++) {
            int col = warp_n + j * 8 + ecol;
            float b0 = 0.f, b1 = 0.f;
            if (c == 0) { b0 = __ldg(bsr + col); b1 = __ldg(bsr + col + 1); }
            int r0 = node0 + warp_m + mt * 16 + erow;
            int r1 = r0 + 8;
            if (r0 < N_NODES) {
                float2 v = make_float2(acc[mt][j][0] + b0, acc[mt][j][1] + b1);
                *(float2*)(out + (size_t)r0 * ROW_F + (size_t)c * H_DIM + col) = v;
            }
            if (r1 < N_NODES) {
                float2 v = make_float2(acc[mt][j][2] + b0, acc[mt][j][3] + b1);
                *(float2*)(out + (size_t)r1 * ROW_F + (size_t)c * H_DIM + col) = v;
            }
        }
    }
}

// ---------------------------------------------------------------------------
// Launch
// ---------------------------------------------------------------------------
extern "C" void kernel_launch(void* const* d_in, const int* in_sizes, int n_in,
                              void* d_out, int out_size) {
    const float* x      = (const float*)d_in[0];
    const void*  ei     = d_in[1];
    const float* Wsrel  = (const float*)d_in[2];
    const float* Wsroot = (const float*)d_in[3];
    const float* bsr    = (const float*)d_in[4];
    const float* Wvrel  = (const float*)d_in[5];
    const float* Wvroot = (const float*)d_in[6];
    float*       out    = (float*)d_out;

    cudaFuncSetAttribute(transform_mma_kernel,
                         cudaFuncAttributeMaxDynamicSharedMemorySize, SM_TOTAL);

    // Phase 0: zero degree counters + dtype detect
    detect_zero_kernel<<<(N_NODES + 255) / 256, 256>>>((const int*)ei);

    // Phase 1: fused prep (x fp16 | W fp16 | ELL scatter)
    fused_prep_kernel<<<PXB + PWB + EB, 256>>>(x, ei, Wsrel, Wsroot, Wvrel, Wvroot);

    // Phase 2: ELL aggregation
    csr_agg_kernel<<<(N_NODES + 3) / 4, 256>>>();

    // Phase 3: transform (fp16 HMMA, 128x128 tile, 3-stage, 2 CTAs/SM)
    {
        dim3 grid((N_NODES + BM - 1) / BM, 4);
        transform_mma_kernel<<<grid, 256, SM_TOTAL>>>(bsr, out);
    }
}